// round 10
// baseline (speedup 1.0000x reference)
#include <cuda_runtime.h>
#include <cstdint>
#include <math.h>

#define NPTS 3072
#define NOUT 16
#define ROWS 8           // i-rows per block
#define CH 256           // j-columns per chunk (= blockDim.x)
#define NCH (NPTS / CH)  // 12 chunks per row
#define CHUNK_FLOATS (CH * NOUT)          // 4096 floats = 16 KB
#define GRID (NPTS / ROWS)                // 384 blocks

// Single-pass: build each 16KB output chunk (zeros + sparse Gaussian values)
// in SMEM, drain via cp.async.bulk (TMA path, bypasses the L1 STG wavefront
// bottleneck that capped STG streams at ~4 TB/s). Double-buffered.
__global__ __launch_bounds__(256) void bulk_edge_kernel(
    const float* __restrict__ coord,
    const float* __restrict__ sig,
    float* __restrict__ out)
{
    __shared__ __align__(16) float buf[2][CHUNK_FLOATS];   // 2 x 16 KB
    __shared__ float4 s_i[ROWS];        // xi, yi, zi, sqi
    __shared__ float  s_inv[NOUT];      // 1/(2*sigma_c^2), reference rounding
    __shared__ float  s_qden, s_lo, s_hi;

    const int tid = threadIdx.x;
    const int i0  = blockIdx.x * ROWS;

    if (tid < NOUT) {
        float s = sig[tid];
        s_inv[tid] = __fdiv_rn(1.0f, __fmul_rn(__fmul_rn(2.0f, s), s));
    }
    if (tid == 0) {
        float sm = sig[NOUT - 1];
        float qd = __fmul_rn(__fmul_rn(2.0f, sm), sm);
        s_qden = qd;
        s_lo = 0.105300f * qd;   // conservative fast-keep bound
        s_hi = 0.105420f * qd;   // conservative fast-drop bound
    }
    if (tid < ROWS) {
        int ig = i0 + tid;
        float x = coord[3 * ig + 0];
        float y = coord[3 * ig + 1];
        float z = coord[3 * ig + 2];
        float sq = __fadd_rn(__fadd_rn(__fmul_rn(x, x), __fmul_rn(y, y)),
                             __fmul_rn(z, z));
        s_i[tid] = make_float4(x, y, z, sq);
    }
    __syncthreads();

    const float lo = s_lo, hi = s_hi, qden = s_qden;

    unsigned smem_buf0, smem_buf1;
    {
        unsigned a;
        asm("{ .reg .u64 t; cvta.to.shared.u64 t, %1; cvt.u32.u64 %0, t; }"
            : "=r"(a) : "l"(&buf[0][0]));
        smem_buf0 = a;
        smem_buf1 = a + CHUNK_FLOATS * 4;
    }

    int iter = 0;
    for (int ch = 0; ch < NCH; ch++) {
        // This thread's j for the whole chunk (reused across ROWS i-rows).
        const int j = ch * CH + tid;
        const float xj = coord[3 * j + 0];
        const float yj = coord[3 * j + 1];
        const float zj = coord[3 * j + 2];
        const float sqj = __fadd_rn(__fadd_rn(__fmul_rn(xj, xj), __fmul_rn(yj, yj)),
                                    __fmul_rn(zj, zj));

        for (int r = 0; r < ROWS; r++, iter++) {
            const int b = iter & 1;

            // Recycle buffer b: its bulk store from iter-2 must be finished.
            if (iter >= 2) {
                if (tid == 0)
                    asm volatile("cp.async.bulk.wait_group 1;" ::: "memory");
                __syncthreads();
            }

            // Zero the chunk (4 STS.128 per thread).
            float4* b4 = reinterpret_cast<float4*>(buf[b]);
            const float4 z4 = make_float4(0.f, 0.f, 0.f, 0.f);
#pragma unroll
            for (int k = 0; k < 4; k++)
                b4[tid + k * CH] = z4;

            // Predicate for pair (i0+r, j) — byte-identical math to prior rounds.
            const int ig = i0 + r;
            const float4 I = s_i[r];
            const float dot = __fmaf_rn(I.z, zj, __fmaf_rn(I.y, yj, __fmul_rn(I.x, xj)));
            float d2 = __fsub_rn(__fadd_rn(I.w, sqj), __fmul_rn(2.0f, dot));
            d2 = fmaxf(d2, 0.0f);

            bool keep;
            if (d2 <= lo) {
                keep = (d2 > 0.0f) && (ig != j);
            } else if (d2 >= hi) {
                keep = false;
            } else {
                const float q = __fdiv_rn(d2, qden);
                if (q <= 0.105340f)       keep = true;
                else if (q >= 0.105380f)  keep = false;
                else                      keep = ((float)exp(-(double)q) >= 0.9f);
                keep = keep && (d2 > 0.0f) && (ig != j);
            }

            if (keep) {
                float v[NOUT];
#pragma unroll
                for (int c = 0; c < NOUT; c++)
                    v[c] = __expf(-__fmul_rn(d2, s_inv[c]));
                float4* dst = reinterpret_cast<float4*>(&buf[b][tid * NOUT]);
                dst[0] = make_float4(v[0],  v[1],  v[2],  v[3]);
                dst[1] = make_float4(v[4],  v[5],  v[6],  v[7]);
                dst[2] = make_float4(v[8],  v[9],  v[10], v[11]);
                dst[3] = make_float4(v[12], v[13], v[14], v[15]);
            }

            __syncthreads();

            if (tid == 0) {
                asm volatile("fence.proxy.async.shared::cta;" ::: "memory");
                float* gdst = out + ((size_t)ig * NPTS + (size_t)ch * CH) * NOUT;
                const unsigned src = (b == 0) ? smem_buf0 : smem_buf1;
                asm volatile(
                    "cp.async.bulk.global.shared::cta.bulk_group [%0], [%1], %2;"
                    :: "l"(gdst), "r"(src), "n"(CHUNK_FLOATS * 4)
                    : "memory");
                asm volatile("cp.async.bulk.commit_group;" ::: "memory");
            }
        }
    }

    // Drain all outstanding bulk stores before the block retires.
    if (tid == 0)
        asm volatile("cp.async.bulk.wait_group 0;" ::: "memory");
    __syncthreads();
}

extern "C" void kernel_launch(void* const* d_in, const int* in_sizes, int n_in,
                              void* d_out, int out_size)
{
    const float* coord = (const float*)d_in[0];   // [3072, 3] fp32
    const float* sig   = (const float*)d_in[1];   // [16] fp32
    float* out = (float*)d_out;                   // [1, 3072, 3072, 16] fp32

    bulk_edge_kernel<<<GRID, 256>>>(coord, sig, out);
}

// round 11
// speedup vs baseline: 1.0146x; 1.0146x over previous
#include <cuda_runtime.h>
#include <cstdint>
#include <math.h>

#define NPTS 3072
#define NOUT 16
#define ROWS 8           // i-rows per block
#define CH 256           // j-columns per chunk (= blockDim.x)
#define NCH (NPTS / CH)  // 12 chunks per row
#define CHUNK_FLOATS (CH * NOUT)          // 4096 floats = 16 KB
#define CHUNK_BYTES (CHUNK_FLOATS * 4)
#define DEPTH 4          // pipeline depth (4 x 16 KB dynamic smem)
#define GRID (NPTS / ROWS)                // 384 blocks
#define SMEM_BYTES (DEPTH * CHUNK_BYTES)  // 64 KB

// Single-pass: build each 16KB output chunk (zeros + sparse Gaussian values)
// in SMEM, drain via cp.async.bulk (TMA path; R10 measured 5.42 TB/s vs 4.2
// for STG). DEPTH=4 buffering to keep more bulk stores in flight per SM.
__global__ __launch_bounds__(256) void bulk_edge_kernel(
    const float* __restrict__ coord,
    const float* __restrict__ sig,
    float* __restrict__ out)
{
    extern __shared__ __align__(16) float buf[];   // DEPTH x CHUNK_FLOATS
    __shared__ float4 s_i[ROWS];        // xi, yi, zi, sqi
    __shared__ float  s_inv[NOUT];      // 1/(2*sigma_c^2), reference rounding
    __shared__ float  s_qden, s_lo, s_hi;

    const int tid = threadIdx.x;
    const int i0  = blockIdx.x * ROWS;

    if (tid < NOUT) {
        float s = sig[tid];
        s_inv[tid] = __fdiv_rn(1.0f, __fmul_rn(__fmul_rn(2.0f, s), s));
    }
    if (tid == 0) {
        float sm = sig[NOUT - 1];
        float qd = __fmul_rn(__fmul_rn(2.0f, sm), sm);
        s_qden = qd;
        s_lo = 0.105300f * qd;   // conservative fast-keep bound
        s_hi = 0.105420f * qd;   // conservative fast-drop bound
    }
    if (tid < ROWS) {
        int ig = i0 + tid;
        float x = coord[3 * ig + 0];
        float y = coord[3 * ig + 1];
        float z = coord[3 * ig + 2];
        float sq = __fadd_rn(__fadd_rn(__fmul_rn(x, x), __fmul_rn(y, y)),
                             __fmul_rn(z, z));
        s_i[tid] = make_float4(x, y, z, sq);
    }
    __syncthreads();

    const float lo = s_lo, hi = s_hi, qden = s_qden;

    unsigned smem_base;
    {
        unsigned a;
        asm("{ .reg .u64 t; cvta.to.shared.u64 t, %1; cvt.u32.u64 %0, t; }"
            : "=r"(a) : "l"(&buf[0]));
        smem_base = a;
    }

    int iter = 0;
    for (int ch = 0; ch < NCH; ch++) {
        // This thread's j for the whole chunk (reused across ROWS i-rows).
        const int j = ch * CH + tid;
        const float xj = coord[3 * j + 0];
        const float yj = coord[3 * j + 1];
        const float zj = coord[3 * j + 2];
        const float sqj = __fadd_rn(__fadd_rn(__fmul_rn(xj, xj), __fmul_rn(yj, yj)),
                                    __fmul_rn(zj, zj));

        for (int r = 0; r < ROWS; r++, iter++) {
            const int b = iter & (DEPTH - 1);
            float* bbuf = buf + (size_t)b * CHUNK_FLOATS;

            // Recycle buffer b: its bulk store from iter-DEPTH must be done.
            if (iter >= DEPTH) {
                if (tid == 0)
                    asm volatile("cp.async.bulk.wait_group %0;"
                                 :: "n"(DEPTH - 1) : "memory");
                __syncthreads();
            }

            // Zero the chunk (4 STS.128 per thread).
            float4* b4 = reinterpret_cast<float4*>(bbuf);
            const float4 z4 = make_float4(0.f, 0.f, 0.f, 0.f);
#pragma unroll
            for (int k = 0; k < 4; k++)
                b4[tid + k * CH] = z4;

            // Predicate for pair (i0+r, j) — byte-identical math to prior rounds.
            const int ig = i0 + r;
            const float4 I = s_i[r];
            const float dot = __fmaf_rn(I.z, zj, __fmaf_rn(I.y, yj, __fmul_rn(I.x, xj)));
            float d2 = __fsub_rn(__fadd_rn(I.w, sqj), __fmul_rn(2.0f, dot));
            d2 = fmaxf(d2, 0.0f);

            bool keep;
            if (d2 <= lo) {
                keep = (d2 > 0.0f) && (ig != j);
            } else if (d2 >= hi) {
                keep = false;
            } else {
                const float q = __fdiv_rn(d2, qden);
                if (q <= 0.105340f)       keep = true;
                else if (q >= 0.105380f)  keep = false;
                else                      keep = ((float)exp(-(double)q) >= 0.9f);
                keep = keep && (d2 > 0.0f) && (ig != j);
            }

            if (keep) {
                float v[NOUT];
#pragma unroll
                for (int c = 0; c < NOUT; c++)
                    v[c] = __expf(-__fmul_rn(d2, s_inv[c]));
                float4* dst = reinterpret_cast<float4*>(&bbuf[tid * NOUT]);
                dst[0] = make_float4(v[0],  v[1],  v[2],  v[3]);
                dst[1] = make_float4(v[4],  v[5],  v[6],  v[7]);
                dst[2] = make_float4(v[8],  v[9],  v[10], v[11]);
                dst[3] = make_float4(v[12], v[13], v[14], v[15]);
            }

            __syncthreads();

            if (tid == 0) {
                asm volatile("fence.proxy.async.shared::cta;" ::: "memory");
                float* gdst = out + ((size_t)ig * NPTS + (size_t)ch * CH) * NOUT;
                const unsigned src = smem_base + (unsigned)b * CHUNK_BYTES;
                asm volatile(
                    "cp.async.bulk.global.shared::cta.bulk_group [%0], [%1], %2;"
                    :: "l"(gdst), "r"(src), "n"(CHUNK_BYTES)
                    : "memory");
                asm volatile("cp.async.bulk.commit_group;" ::: "memory");
            }
        }
    }

    // Drain all outstanding bulk stores before the block retires.
    if (tid == 0)
        asm volatile("cp.async.bulk.wait_group 0;" ::: "memory");
    __syncthreads();
}

extern "C" void kernel_launch(void* const* d_in, const int* in_sizes, int n_in,
                              void* d_out, int out_size)
{
    const float* coord = (const float*)d_in[0];   // [3072, 3] fp32
    const float* sig   = (const float*)d_in[1];   // [16] fp32
    float* out = (float*)d_out;                   // [1, 3072, 3072, 16] fp32

    cudaFuncSetAttribute(bulk_edge_kernel,
                         cudaFuncAttributeMaxDynamicSharedMemorySize, SMEM_BYTES);
    bulk_edge_kernel<<<GRID, 256, SMEM_BYTES>>>(coord, sig, out);
}